// round 1
// baseline (speedup 1.0000x reference)
#include <cuda_runtime.h>
#include <cstdint>

// Problem dims
constexpr int Bsz   = 32;
constexpr int Tt    = 2048;
constexpr int STATE = 128;
constexpr int ACTd  = 16;
constexpr int LAT   = 256;
constexpr int ENC   = 1024;
constexpr int MTOK  = Bsz * Tt;          // 65536 tokens
constexpr int INW   = STATE + 2 * ACTd;  // 160 = padded_input row width

// Scratch (device globals: allocation-free rule)
__device__ float g_h1[(size_t)MTOK * ENC];
__device__ float g_h2[(size_t)MTOK * ENC];
__device__ float g_z [(size_t)MTOK * LAT];
__device__ float g_bu[(size_t)MTOK * LAT];
__device__ float g_z2[(size_t)MTOK * LAT];

// ---------------------------------------------------------------------------
// Tiled SGEMM: C[M,N] = act(A[M,K] @ W[K,N] + bias)
// BM=BN=128, BK=8, 256 threads, 8x8 register tile per thread.
// M, N, K assumed multiples of tile dims (true for all calls here).
// A has row stride lda (handles the strided slices of padded_input).
// ---------------------------------------------------------------------------
template<bool TANH, bool HASBIAS>
__global__ __launch_bounds__(256, 2)
void gemm_kernel(const float* __restrict__ A, int lda,
                 const float* __restrict__ W,
                 const float* __restrict__ bias,
                 float* __restrict__ C, int N, int K)
{
    __shared__ float As[8][128];   // transposed A tile: As[k][m]
    __shared__ float Bs[8][128];

    const int tid = threadIdx.x;
    const int bx = blockIdx.x, by = blockIdx.y;

    const float* Ab = A + (size_t)by * 128 * lda;
    const float* Wb = W + bx * 128;

    // global->shared load mapping (each thread: 4 A elems, 4 W elems)
    const int aRow = tid >> 1;          // 0..127
    const int aCol = (tid & 1) << 2;    // 0 or 4
    const int bRow = tid >> 5;          // 0..7
    const int bCol = (tid & 31) << 2;   // 0..124

    // compute mapping: 16x16 thread grid of 8x8 tiles
    const int tr = (tid >> 4) << 3;     // 0..120
    const int tc = (tid & 15) << 3;     // 0..120

    float acc[8][8];
#pragma unroll
    for (int i = 0; i < 8; i++)
#pragma unroll
        for (int j = 0; j < 8; j++) acc[i][j] = 0.0f;

    for (int kt = 0; kt < K; kt += 8) {
        float4 av = *reinterpret_cast<const float4*>(Ab + (size_t)aRow * lda + kt + aCol);
        float4 bv = *reinterpret_cast<const float4*>(Wb + (size_t)(kt + bRow) * N + bCol);

        As[aCol + 0][aRow] = av.x;
        As[aCol + 1][aRow] = av.y;
        As[aCol + 2][aRow] = av.z;
        As[aCol + 3][aRow] = av.w;
        *reinterpret_cast<float4*>(&Bs[bRow][bCol]) = bv;
        __syncthreads();

#pragma unroll
        for (int k = 0; k < 8; k++) {
            float4 a0 = *reinterpret_cast<const float4*>(&As[k][tr]);
            float4 a1 = *reinterpret_cast<const float4*>(&As[k][tr + 4]);
            float4 b0 = *reinterpret_cast<const float4*>(&Bs[k][tc]);
            float4 b1 = *reinterpret_cast<const float4*>(&Bs[k][tc + 4]);
            float am[8] = {a0.x, a0.y, a0.z, a0.w, a1.x, a1.y, a1.z, a1.w};
            float bn[8] = {b0.x, b0.y, b0.z, b0.w, b1.x, b1.y, b1.z, b1.w};
#pragma unroll
            for (int i = 0; i < 8; i++)
#pragma unroll
                for (int j = 0; j < 8; j++)
                    acc[i][j] = fmaf(am[i], bn[j], acc[i][j]);
        }
        __syncthreads();
    }

    // epilogue: bias + tanh, write out
    float* Cb = C + (size_t)(by * 128 + tr) * N + bx * 128 + tc;
#pragma unroll
    for (int i = 0; i < 8; i++) {
#pragma unroll
        for (int j = 0; j < 8; j++) {
            float v = acc[i][j];
            if (HASBIAS) v += bias[bx * 128 + tc + j];
            if (TANH)    v = tanhf(v);
            Cb[(size_t)i * N + j] = v;
        }
    }
}

// ---------------------------------------------------------------------------
// Recurrence scan: one thread per (batch, latent-channel).
//   t <= nwarmup : out[t] = a*z[t]   + bu[t]
//   t >  nwarmup : out[t] = a*out[t-1] + bu[t]
// a = clip(a_diag, -0.95, 0.95)
// ---------------------------------------------------------------------------
__global__ void scan_kernel(const float* __restrict__ z,
                            const float* __restrict__ bu,
                            const float* __restrict__ a_diag,
                            const int*   __restrict__ nwp,
                            float* __restrict__ z2)
{
    const int l = threadIdx.x;   // 0..255
    const int b = blockIdx.x;    // 0..31
    const int nw = *nwp;         // first 4 bytes (works for i32/i64 LE scalar)

    float a = a_diag[l];
    a = fminf(0.95f, fmaxf(-0.95f, a));

    const size_t base = ((size_t)b * Tt) * LAT + l;
    float prev = z[base];        // scan init carry = z[:,0,:]

#pragma unroll 4
    for (int t = 0; t < Tt; ++t) {
        const size_t idx = base + (size_t)t * LAT;
        float inp = (t <= nw) ? z[idx] : prev;
        float out = fmaf(a, inp, bu[idx]);
        z2[idx] = out;
        prev = out;
    }
}

// ---------------------------------------------------------------------------
// Launch
// ---------------------------------------------------------------------------
extern "C" void kernel_launch(void* const* d_in, const int* in_sizes, int n_in,
                              void* d_out, int out_size)
{
    (void)in_sizes; (void)n_in; (void)out_size;

    const float* pin   = (const float*)d_in[0];
    const float* ew1   = (const float*)d_in[1];
    const float* eb1   = (const float*)d_in[2];
    const float* ew2   = (const float*)d_in[3];
    const float* eb2   = (const float*)d_in[4];
    const float* ew3   = (const float*)d_in[5];
    const float* eb3   = (const float*)d_in[6];
    const float* adiag = (const float*)d_in[7];
    const float* Bw    = (const float*)d_in[8];
    const float* dw1   = (const float*)d_in[9];
    const float* db1   = (const float*)d_in[10];
    const float* dw2   = (const float*)d_in[11];
    const float* db2   = (const float*)d_in[12];
    const float* dw3   = (const float*)d_in[13];
    const float* db3   = (const float*)d_in[14];
    const int*   nw    = (const int*)d_in[15];
    float* out = (float*)d_out;

    float *h1, *h2, *z, *bu, *z2;
    cudaGetSymbolAddress((void**)&h1, g_h1);
    cudaGetSymbolAddress((void**)&h2, g_h2);
    cudaGetSymbolAddress((void**)&z,  g_z);
    cudaGetSymbolAddress((void**)&bu, g_bu);
    cudaGetSymbolAddress((void**)&z2, g_z2);

    const dim3 blk(256);
    const int MBLK = MTOK / 128;  // 512

    // Encoder: x -> h1 -> h2 -> z   (tanh each)
    gemm_kernel<true,  true ><<<dim3(ENC / 128,   MBLK), blk>>>(pin, INW, ew1, eb1, h1, ENC, STATE);
    gemm_kernel<true,  true ><<<dim3(ENC / 128,   MBLK), blk>>>(h1,  ENC, ew2, eb2, h2, ENC, ENC);
    gemm_kernel<true,  true ><<<dim3(LAT / 128,   MBLK), blk>>>(h2,  ENC, ew3, eb3, z,  LAT, ENC);

    // Bu = u_t1 @ B_w  (u slice: cols [STATE+ACT, STATE+2*ACT) of padded_input)
    gemm_kernel<false, false><<<dim3(LAT / 128,   MBLK), blk>>>(pin + STATE + ACTd, INW, Bw, nullptr, bu, LAT, ACTd);

    // Recurrence
    scan_kernel<<<Bsz, LAT>>>(z, bu, adiag, nw, z2);

    // Decoder: z2 -> h1 -> h2 -> out   (tanh, tanh, linear+bias)
    gemm_kernel<true,  true ><<<dim3(ENC / 128,   MBLK), blk>>>(z2, LAT, dw1, db1, h1, ENC, LAT);
    gemm_kernel<true,  true ><<<dim3(ENC / 128,   MBLK), blk>>>(h1, ENC, dw2, db2, h2, ENC, ENC);
    gemm_kernel<false, true ><<<dim3(STATE / 128, MBLK), blk>>>(h2, ENC, dw3, db3, out, STATE, ENC);
}

// round 4
// speedup vs baseline: 3.9806x; 3.9806x over previous
#include <cuda_runtime.h>
#include <cstdint>

// ---------------------------------------------------------------------------
// Arch-feature gate: tcgen05/TMEM only exist in the sm_103a/sm_100a feature
// set. A compute_103 (family) PTX pass must not see those instructions.
// ---------------------------------------------------------------------------
#if defined(__CUDA_ARCH_FEAT_SM103_ALL) || defined(__CUDA_ARCH_FEAT_SM100_ALL) || \
    defined(__CUDA_ARCH_FEAT_SM101_ALL)
#define HAS_TC 1
#else
#define HAS_TC 0
#endif

// ---------------------------------------------------------------------------
// Problem dims
// ---------------------------------------------------------------------------
constexpr int Bsz   = 32;
constexpr int Tt    = 2048;
constexpr int STATE = 128;
constexpr int ACTd  = 16;
constexpr int LAT   = 256;
constexpr int ENC   = 1024;
constexpr int MTOK  = Bsz * Tt;          // 65536 tokens
constexpr int INW   = STATE + 2 * ACTd;  // 160

// ---------------------------------------------------------------------------
// Scratch (device globals: allocation-free rule)
// ---------------------------------------------------------------------------
__device__ float g_h1[(size_t)MTOK * ENC];
__device__ float g_h2[(size_t)MTOK * ENC];
__device__ float g_z [(size_t)MTOK * LAT];
__device__ float g_bu[(size_t)MTOK * LAT];
__device__ float g_z2[(size_t)MTOK * LAT];
// transposed (and tf32-rounded) weights: WT[n][k]
__device__ float g_t_ew1[(size_t)ENC * STATE];
__device__ float g_t_ew2[(size_t)ENC * ENC];
__device__ float g_t_ew3[(size_t)LAT * ENC];
__device__ float g_t_dw1[(size_t)ENC * LAT];
__device__ float g_t_dw2[(size_t)ENC * ENC];
__device__ float g_t_dw3[(size_t)STATE * ENC];

// ---------------------------------------------------------------------------
// Helpers
// ---------------------------------------------------------------------------
__device__ __forceinline__ float rna_tf32(float x) {
    float r;
    asm("cvt.rna.tf32.f32 %0, %1;" : "=f"(r) : "f"(x));
    return r;
}
#define SWZ128(off) ((off) ^ (((off) >> 3) & 0x70))

#if HAS_TC
__device__ __forceinline__ uint32_t smem_u32(const void* p) {
    uint32_t a;
    asm("{ .reg .u64 t; cvta.to.shared.u64 t, %1; cvt.u32.u64 %0, t; }" : "=r"(a) : "l"(p));
    return a;
}
__device__ __forceinline__ uint32_t elect_one() {
    uint32_t p;
    asm volatile("{ .reg .pred p; elect.sync _|p, 0xFFFFFFFF; selp.b32 %0, 1, 0, p; }" : "=r"(p));
    return p;
}

// 64-bit SMEM descriptor: SW128, Blackwell, LBO=1, SBO=64 (128B rows, 8-row atom)
static constexpr uint64_t DESC_BASE_SW128 =
    (uint64_t(2) << 61) | (uint64_t(1) << 46) | (uint64_t(64) << 32) | (uint64_t(1) << 16);
__device__ __forceinline__ uint64_t make_desc(uint32_t addr) {
    return DESC_BASE_SW128 | ((uint64_t)(addr >> 4) & 0x3FFF);
}

#define MBAR_INIT(a, c) \
    asm volatile("mbarrier.init.shared.b64 [%0], %1;" :: "r"(a), "r"(c) : "memory")
#define MBAR_WAIT(a, ph) do {                                                   \
    uint32_t _m = (a), _p = (ph), _d;                                           \
    asm volatile("{ .reg .pred p; mbarrier.try_wait.parity.acquire.cta.shared::cta.b64 p, [%1], %2; selp.b32 %0, 1, 0, p; }" \
                 : "=r"(_d) : "r"(_m), "r"(_p) : "memory");                     \
    if (!_d) {                                                                  \
        asm volatile("{ .reg .pred P;\nWL_%=:\n mbarrier.try_wait.parity.acquire.cta.shared::cta.b64 P, [%0], %1, 0x989680;\n @P bra.uni WD_%=;\n bra.uni WL_%=;\nWD_%=:\n}" \
                     :: "r"(_m), "r"(_p) : "memory");                           \
    } } while (0)

#define TC_ALLOC(sa, n) \
    asm volatile("tcgen05.alloc.cta_group::1.sync.aligned.shared::cta.b32 [%0], %1;" :: "r"(sa), "r"(n) : "memory")
#define TC_RELINQ() \
    asm volatile("tcgen05.relinquish_alloc_permit.cta_group::1.sync.aligned;")
#define TC_DEALLOC(t, n) \
    asm volatile("tcgen05.dealloc.cta_group::1.sync.aligned.b32 %0, %1;" :: "r"(t), "r"(n))
#define TC_COMMIT(mb) \
    asm volatile("tcgen05.commit.cta_group::1.mbarrier::arrive::one.shared::cluster.b64 [%0];" :: "r"(mb) : "memory")
#define TC_WAIT_LD() asm volatile("tcgen05.wait::ld.sync.aligned;" ::: "memory")
#define TC_FENCE_AFTER() asm volatile("tcgen05.fence::after_thread_sync;" ::: "memory")
#define FENCE_ASYNC() asm volatile("fence.proxy.async.shared::cta;" ::: "memory")

#define TC_LD_X32(r, ta) \
    asm volatile("tcgen05.ld.sync.aligned.32x32b.x32.b32 " \
        "{%0,%1,%2,%3,%4,%5,%6,%7,%8,%9,%10,%11,%12,%13,%14,%15," \
        "%16,%17,%18,%19,%20,%21,%22,%23,%24,%25,%26,%27,%28,%29,%30,%31}, [%32];" \
        : "=r"((r)[0]),"=r"((r)[1]),"=r"((r)[2]),"=r"((r)[3]),"=r"((r)[4]),"=r"((r)[5]),"=r"((r)[6]),"=r"((r)[7]), \
          "=r"((r)[8]),"=r"((r)[9]),"=r"((r)[10]),"=r"((r)[11]),"=r"((r)[12]),"=r"((r)[13]),"=r"((r)[14]),"=r"((r)[15]), \
          "=r"((r)[16]),"=r"((r)[17]),"=r"((r)[18]),"=r"((r)[19]),"=r"((r)[20]),"=r"((r)[21]),"=r"((r)[22]),"=r"((r)[23]), \
          "=r"((r)[24]),"=r"((r)[25]),"=r"((r)[26]),"=r"((r)[27]),"=r"((r)[28]),"=r"((r)[29]),"=r"((r)[30]),"=r"((r)[31]) \
        : "r"(ta))

__device__ __forceinline__ void mma_tf32_ss(uint32_t d, uint64_t ad, uint64_t bd,
                                            uint32_t idesc, uint32_t en) {
    asm volatile(
        "{\n\t.reg .pred p;\n\tsetp.ne.u32 p, %5, 0;\n\t"
        "tcgen05.mma.cta_group::1.kind::tf32 [%0], %1, %2, %3, {%4, %4, %4, %4}, p;\n\t}"
        :: "r"(d), "l"(ad), "l"(bd), "r"(idesc), "r"(0u), "r"(en) : "memory");
}
#endif  // HAS_TC

// ---------------------------------------------------------------------------
// Weight transpose + tf32 rounding: out[n*K + k] = rna(in[k*N + n])
// ---------------------------------------------------------------------------
__global__ void transpose_round(const float* __restrict__ in, float* __restrict__ out,
                                int K, int N) {
    __shared__ float t[32][33];
    const int kb = blockIdx.x * 32, nb = blockIdx.y * 32;
    const int x = threadIdx.x, y = threadIdx.y;  // 32x8
#pragma unroll
    for (int i = y; i < 32; i += 8)
        t[i][x] = rna_tf32(in[(size_t)(kb + i) * N + nb + x]);
    __syncthreads();
#pragma unroll
    for (int i = y; i < 32; i += 8)
        out[(size_t)(nb + i) * K + kb + x] = t[x][i];
}

// ---------------------------------------------------------------------------
// GEMM:  C[M,N] = act(A[M,K] @ W[K,N] + bias)
// A: row-major, stride lda.  BT: pre-transposed W^T [N][K] row-major.
// tcgen05 tf32 path on sm_103a; SIMT fallback body otherwise (same semantics).
// CTA tile: 128(M) x NT(N).
// ---------------------------------------------------------------------------
template<int NT, bool TANH, bool HASBIAS>
__global__ __launch_bounds__(256)
void tc_gemm(const float* __restrict__ A, int lda,
             const float* __restrict__ BT,
             const float* __restrict__ bias,
             float* __restrict__ C, int N, int K)
{
    const int tid = threadIdx.x;
    const int nb = blockIdx.x * NT;
    const int mb = blockIdx.y * 128;

#if HAS_TC
    extern __shared__ char dynsm[];
    const uint32_t smem_base = smem_u32(dynsm);
    const int wid = tid >> 5, lane = tid & 31;

    constexpr int ABYTES = 128 * 128;        // 16KB (128 rows x 32 tf32)
    constexpr int BBYTES = NT * 128;
    constexpr int BUFB   = ABYTES + BBYTES;

    const uint32_t s_tmemptr = smem_base;
    const uint32_t s_mbar0   = smem_base + 8;
    const uint32_t s_mbar1   = smem_base + 16;
    const uint32_t s_buf0    = (smem_base + 1024 + 1023) & ~1023u;  // 1KB aligned
    char* buf_ptr = dynsm + (s_buf0 - smem_base);

    if (tid == 0) { MBAR_INIT(s_mbar0, 1); MBAR_INIT(s_mbar1, 1); }
    if (wid == 0) { TC_ALLOC(s_tmemptr, NT); TC_RELINQ(); }
    __syncthreads();
    uint32_t tmem;
    asm volatile("ld.shared.b32 %0, [%1];" : "=r"(tmem) : "r"(s_tmemptr));

    const int KT = K >> 5;
    int ph0 = 0, ph1 = 0;
    constexpr uint32_t IDESC =
        (1u << 4) | (2u << 7) | (2u << 10) | ((NT / 8) << 17) | (8u << 24);

    for (int t = 0; t < KT; ++t) {
        const int buf = t & 1;
        const uint32_t sb = s_buf0 + buf * BUFB;
        char* sp = buf_ptr + buf * BUFB;

        if (t >= 2) {
            if (buf == 0) { MBAR_WAIT(s_mbar0, ph0); ph0 ^= 1; }
            else          { MBAR_WAIT(s_mbar1, ph1); ph1 ^= 1; }
        }

        // fill A tile: 128 rows x 32 cols, rounded to tf32, SW128 swizzled
        const float* Ag = A + (size_t)mb * lda + t * 32;
#pragma unroll
        for (int i = 0; i < 4; i++) {
            const int idx = tid + i * 256;         // 0..1023 float4s
            const int row = idx >> 3, c4 = idx & 7;
            float4 v = *reinterpret_cast<const float4*>(Ag + (size_t)row * lda + c4 * 4);
            v.x = rna_tf32(v.x); v.y = rna_tf32(v.y);
            v.z = rna_tf32(v.z); v.w = rna_tf32(v.w);
            const uint32_t off = SWZ128((uint32_t)(row * 128 + c4 * 16));
            *reinterpret_cast<float4*>(sp + off) = v;
        }
        // fill B tile: NT rows x 32 cols from WT (already rounded)
        const float* Bg = BT + (size_t)nb * K + t * 32;
#pragma unroll
        for (int i = 0; i < NT / 32; i++) {
            const int idx = tid + i * 256;
            const int row = idx >> 3, c4 = idx & 7;
            float4 v = *reinterpret_cast<const float4*>(Bg + (size_t)row * K + c4 * 4);
            const uint32_t off = SWZ128((uint32_t)(row * 128 + c4 * 16));
            *reinterpret_cast<float4*>(sp + ABYTES + off) = v;
        }
        __syncthreads();
        FENCE_ASYNC();

        if (wid == 0 && elect_one()) {
            const uint64_t ad = make_desc(sb);
            const uint64_t bd = make_desc(sb + ABYTES);
#pragma unroll
            for (int s = 0; s < 4; s++)            // 4 x K=8 tf32 MMAs
                mma_tf32_ss(tmem, ad + s * 2, bd + s * 2, IDESC,
                            (t > 0 || s > 0) ? 1u : 0u);
            if (buf == 0) TC_COMMIT(s_mbar0); else TC_COMMIT(s_mbar1);
        }
    }

    // drain outstanding MMA groups
    if (KT >= 2) {
        const int b = (KT - 2) & 1;
        if (b == 0) { MBAR_WAIT(s_mbar0, ph0); ph0 ^= 1; }
        else        { MBAR_WAIT(s_mbar1, ph1); ph1 ^= 1; }
    }
    {
        const int b = (KT - 1) & 1;
        if (b == 0) { MBAR_WAIT(s_mbar0, ph0); ph0 ^= 1; }
        else        { MBAR_WAIT(s_mbar1, ph1); ph1 ^= 1; }
    }
    TC_FENCE_AFTER();

    // epilogue: warps 0-3 cols [0,NT/2), warps 4-7 cols [NT/2,NT)
    const int half = wid >> 2;
    const int grow = mb + (wid & 3) * 32 + lane;
#pragma unroll
    for (int cc = 0; cc < NT / 2; cc += 32) {
        const int c0 = half * (NT / 2) + cc;
        uint32_t regs[32];
        TC_LD_X32(regs, tmem + c0);
        TC_WAIT_LD();
        float* Crow = C + (size_t)grow * N + nb + c0;
#pragma unroll
        for (int q = 0; q < 8; q++) {
            float4 o;
            float a0 = __uint_as_float(regs[4 * q + 0]);
            float a1 = __uint_as_float(regs[4 * q + 1]);
            float a2 = __uint_as_float(regs[4 * q + 2]);
            float a3 = __uint_as_float(regs[4 * q + 3]);
            if (HASBIAS) {
                a0 += bias[nb + c0 + 4 * q + 0];
                a1 += bias[nb + c0 + 4 * q + 1];
                a2 += bias[nb + c0 + 4 * q + 2];
                a3 += bias[nb + c0 + 4 * q + 3];
            }
            if (TANH) { a0 = tanhf(a0); a1 = tanhf(a1); a2 = tanhf(a2); a3 = tanhf(a3); }
            o.x = a0; o.y = a1; o.z = a2; o.w = a3;
            *reinterpret_cast<float4*>(Crow + 4 * q) = o;
        }
    }
    __syncthreads();
    if (wid == 0) TC_DEALLOC(tmem, NT);

#else  // ---------------- SIMT fallback body (non-a pass) ----------------
    __shared__ float As[8][128];
    __shared__ float Bs[8][128];

    const int aRow = tid >> 1, aCol = (tid & 1) << 2;   // A loads
    const int bRow = tid >> 1, bCol = (tid & 1) << 2;   // BT loads (along K)
    const int tr = (tid >> 4) << 3, tc = (tid & 15) << 3;

    for (int sub = 0; sub < NT / 128; ++sub) {
        const int nb2 = nb + sub * 128;
        const float* Ab  = A + (size_t)mb * lda;
        const float* BTb = BT + (size_t)nb2 * K;

        float acc[8][8];
#pragma unroll
        for (int i = 0; i < 8; i++)
#pragma unroll
            for (int j = 0; j < 8; j++) acc[i][j] = 0.0f;

        for (int kt = 0; kt < K; kt += 8) {
            float4 av = *reinterpret_cast<const float4*>(Ab + (size_t)aRow * lda + kt + aCol);
            float4 bv = *reinterpret_cast<const float4*>(BTb + (size_t)bRow * K + kt + bCol);
            As[aCol + 0][aRow] = av.x; As[aCol + 1][aRow] = av.y;
            As[aCol + 2][aRow] = av.z; As[aCol + 3][aRow] = av.w;
            Bs[bCol + 0][bRow] = bv.x; Bs[bCol + 1][bRow] = bv.y;
            Bs[bCol + 2][bRow] = bv.z; Bs[bCol + 3][bRow] = bv.w;
            __syncthreads();
#pragma unroll
            for (int k = 0; k < 8; k++) {
                float4 a0 = *reinterpret_cast<const float4*>(&As[k][tr]);
                float4 a1 = *reinterpret_cast<const float4*>(&As[k][tr + 4]);
                float4 b0 = *reinterpret_cast<const float4*>(&Bs[k][tc]);
                float4 b1 = *reinterpret_cast<const float4*>(&Bs[k][tc + 4]);
                float am[8] = {a0.x, a0.y, a0.z, a0.w, a1.x, a1.y, a1.z, a1.w};
                float bn[8] = {b0.x, b0.y, b0.z, b0.w, b1.x, b1.y, b1.z, b1.w};
#pragma unroll
                for (int i = 0; i < 8; i++)
#pragma unroll
                    for (int j = 0; j < 8; j++)
                        acc[i][j] = fmaf(am[i], bn[j], acc[i][j]);
            }
            __syncthreads();
        }
        float* Cb = C + (size_t)(mb + tr) * N + nb2 + tc;
#pragma unroll
        for (int i = 0; i < 8; i++)
#pragma unroll
            for (int j = 0; j < 8; j++) {
                float v = acc[i][j];
                if (HASBIAS) v += bias[nb2 + tc + j];
                if (TANH)    v = tanhf(v);
                Cb[(size_t)i * N + j] = v;
            }
    }
#endif
}

// ---------------------------------------------------------------------------
// SIMT GEMM (kept for the tiny K=16 Bu matmul; W in original [K][N] layout)
// ---------------------------------------------------------------------------
template<bool TANH, bool HASBIAS>
__global__ __launch_bounds__(256, 2)
void gemm_kernel(const float* __restrict__ A, int lda,
                 const float* __restrict__ W,
                 const float* __restrict__ bias,
                 float* __restrict__ C, int N, int K)
{
    __shared__ float As[8][128];
    __shared__ float Bs[8][128];
    const int tid = threadIdx.x;
    const int bx = blockIdx.x, by = blockIdx.y;
    const float* Ab = A + (size_t)by * 128 * lda;
    const float* Wb = W + bx * 128;
    const int aRow = tid >> 1, aCol = (tid & 1) << 2;
    const int bRow = tid >> 5, bCol = (tid & 31) << 2;
    const int tr = (tid >> 4) << 3, tc = (tid & 15) << 3;
    float acc[8][8];
#pragma unroll
    for (int i = 0; i < 8; i++)
#pragma unroll
        for (int j = 0; j < 8; j++) acc[i][j] = 0.0f;
    for (int kt = 0; kt < K; kt += 8) {
        float4 av = *reinterpret_cast<const float4*>(Ab + (size_t)aRow * lda + kt + aCol);
        float4 bv = *reinterpret_cast<const float4*>(Wb + (size_t)(kt + bRow) * N + bCol);
        As[aCol + 0][aRow] = av.x; As[aCol + 1][aRow] = av.y;
        As[aCol + 2][aRow] = av.z; As[aCol + 3][aRow] = av.w;
        *reinterpret_cast<float4*>(&Bs[bRow][bCol]) = bv;
        __syncthreads();
#pragma unroll
        for (int k = 0; k < 8; k++) {
            float4 a0 = *reinterpret_cast<const float4*>(&As[k][tr]);
            float4 a1 = *reinterpret_cast<const float4*>(&As[k][tr + 4]);
            float4 b0 = *reinterpret_cast<const float4*>(&Bs[k][tc]);
            float4 b1 = *reinterpret_cast<const float4*>(&Bs[k][tc + 4]);
            float am[8] = {a0.x, a0.y, a0.z, a0.w, a1.x, a1.y, a1.z, a1.w};
            float bn[8] = {b0.x, b0.y, b0.z, b0.w, b1.x, b1.y, b1.z, b1.w};
#pragma unroll
            for (int i = 0; i < 8; i++)
#pragma unroll
                for (int j = 0; j < 8; j++)
                    acc[i][j] = fmaf(am[i], bn[j], acc[i][j]);
        }
        __syncthreads();
    }
    float* Cb = C + (size_t)(by * 128 + tr) * N + bx * 128 + tc;
#pragma unroll
    for (int i = 0; i < 8; i++)
#pragma unroll
        for (int j = 0; j < 8; j++) {
            float v = acc[i][j];
            if (HASBIAS) v += bias[bx * 128 + tc + j];
            if (TANH)    v = tanhf(v);
            Cb[(size_t)i * N + j] = v;
        }
}

// ---------------------------------------------------------------------------
// Recurrence scan
// ---------------------------------------------------------------------------
__global__ void scan_kernel(const float* __restrict__ z,
                            const float* __restrict__ bu,
                            const float* __restrict__ a_diag,
                            const int*   __restrict__ nwp,
                            float* __restrict__ z2)
{
    const int l = threadIdx.x;
    const int b = blockIdx.x;
    const int nw = *nwp;
    float a = a_diag[l];
    a = fminf(0.95f, fmaxf(-0.95f, a));
    const size_t base = ((size_t)b * Tt) * LAT + l;
    float prev = z[base];
#pragma unroll 4
    for (int t = 0; t < Tt; ++t) {
        const size_t idx = base + (size_t)t * LAT;
        float inp = (t <= nw) ? z[idx] : prev;
        float out = fmaf(a, inp, bu[idx]);
        z2[idx] = out;
        prev = out;
    }
}

// ---------------------------------------------------------------------------
// Launch
// ---------------------------------------------------------------------------
extern "C" void kernel_launch(void* const* d_in, const int* in_sizes, int n_in,
                              void* d_out, int out_size)
{
    (void)in_sizes; (void)n_in; (void)out_size;
    const float* pin   = (const float*)d_in[0];
    const float* ew1   = (const float*)d_in[1];
    const float* eb1   = (const float*)d_in[2];
    const float* ew2   = (const float*)d_in[3];
    const float* eb2   = (const float*)d_in[4];
    const float* ew3   = (const float*)d_in[5];
    const float* eb3   = (const float*)d_in[6];
    const float* adiag = (const float*)d_in[7];
    const float* Bw    = (const float*)d_in[8];
    const float* dw1   = (const float*)d_in[9];
    const float* db1   = (const float*)d_in[10];
    const float* dw2   = (const float*)d_in[11];
    const float* db2   = (const float*)d_in[12];
    const float* dw3   = (const float*)d_in[13];
    const float* db3   = (const float*)d_in[14];
    const int*   nw    = (const int*)d_in[15];
    float* out = (float*)d_out;

    float *h1, *h2, *z, *bu, *z2;
    float *t_ew1, *t_ew2, *t_ew3, *t_dw1, *t_dw2, *t_dw3;
    cudaGetSymbolAddress((void**)&h1, g_h1);
    cudaGetSymbolAddress((void**)&h2, g_h2);
    cudaGetSymbolAddress((void**)&z,  g_z);
    cudaGetSymbolAddress((void**)&bu, g_bu);
    cudaGetSymbolAddress((void**)&z2, g_z2);
    cudaGetSymbolAddress((void**)&t_ew1, g_t_ew1);
    cudaGetSymbolAddress((void**)&t_ew2, g_t_ew2);
    cudaGetSymbolAddress((void**)&t_ew3, g_t_ew3);
    cudaGetSymbolAddress((void**)&t_dw1, g_t_dw1);
    cudaGetSymbolAddress((void**)&t_dw2, g_t_dw2);
    cudaGetSymbolAddress((void**)&t_dw3, g_t_dw3);

    // dynamic smem: 2KB header/align slack + 2 double buffers
    const int SMEM256 = 2048 + 2 * (128 * 128 + 256 * 128);  // 100352
    const int SMEM128 = 2048 + 2 * (128 * 128 + 128 * 128);  // 67584
    cudaFuncSetAttribute(tc_gemm<256, true,  true>,
                         cudaFuncAttributeMaxDynamicSharedMemorySize, SMEM256);
    cudaFuncSetAttribute(tc_gemm<128, false, true>,
                         cudaFuncAttributeMaxDynamicSharedMemorySize, SMEM128);

    const dim3 tb(32, 8);
    // transpose + tf32-round weights: in[K,N] -> out[N,K]
    transpose_round<<<dim3(STATE / 32, ENC / 32), tb>>>(ew1, t_ew1, STATE, ENC);
    transpose_round<<<dim3(ENC / 32,   ENC / 32), tb>>>(ew2, t_ew2, ENC,   ENC);
    transpose_round<<<dim3(ENC / 32,   LAT / 32), tb>>>(ew3, t_ew3, ENC,   LAT);
    transpose_round<<<dim3(LAT / 32,   ENC / 32), tb>>>(dw1, t_dw1, LAT,   ENC);
    transpose_round<<<dim3(ENC / 32,   ENC / 32), tb>>>(dw2, t_dw2, ENC,   ENC);
    transpose_round<<<dim3(ENC / 32, STATE / 32), tb>>>(dw3, t_dw3, ENC,   STATE);

    const int MBLK = MTOK / 128;  // 512

    // Encoder
    tc_gemm<256, true, true><<<dim3(ENC / 256, MBLK), 256, SMEM256>>>(
        pin, INW, t_ew1, eb1, h1, ENC, STATE);
    tc_gemm<256, true, true><<<dim3(ENC / 256, MBLK), 256, SMEM256>>>(
        h1, ENC, t_ew2, eb2, h2, ENC, ENC);
    tc_gemm<256, true, true><<<dim3(LAT / 256, MBLK), 256, SMEM256>>>(
        h2, ENC, t_ew3, eb3, z, LAT, ENC);

    // Bu = u @ B_w  (K=16, SIMT)
    gemm_kernel<false, false><<<dim3(LAT / 128, MBLK), 256>>>(
        pin + STATE + ACTd, INW, Bw, nullptr, bu, LAT, ACTd);

    // Recurrence
    scan_kernel<<<Bsz, LAT>>>(z, bu, adiag, nw, z2);

    // Decoder
    tc_gemm<256, true, true><<<dim3(ENC / 256, MBLK), 256, SMEM256>>>(
        z2, LAT, t_dw1, db1, h1, ENC, LAT);
    tc_gemm<256, true, true><<<dim3(ENC / 256, MBLK), 256, SMEM256>>>(
        h1, ENC, t_dw2, db2, h2, ENC, ENC);
    tc_gemm<128, false, true><<<dim3(STATE / 128, MBLK), 256, SMEM128>>>(
        h2, ENC, t_dw3, db3, out, STATE, ENC);
}

// round 5
// speedup vs baseline: 11.4223x; 2.8695x over previous
#include <cuda_runtime.h>
#include <cstdint>

// ---------------------------------------------------------------------------
// Arch-feature gate: tcgen05/TMEM only exist in the sm_103a/sm_100a feature
// set. A compute_103 (family) PTX pass must not see those instructions.
// ---------------------------------------------------------------------------
#if defined(__CUDA_ARCH_FEAT_SM103_ALL) || defined(__CUDA_ARCH_FEAT_SM100_ALL) || \
    defined(__CUDA_ARCH_FEAT_SM101_ALL)
#define HAS_TC 1
#else
#define HAS_TC 0
#endif

// ---------------------------------------------------------------------------
// Problem dims
// ---------------------------------------------------------------------------
constexpr int Bsz   = 32;
constexpr int Tt    = 2048;
constexpr int STATE = 128;
constexpr int ACTd  = 16;
constexpr int LAT   = 256;
constexpr int ENC   = 1024;
constexpr int MTOK  = Bsz * Tt;          // 65536 tokens
constexpr int INW   = STATE + 2 * ACTd;  // 160
constexpr int NCH   = 16;                // scan chunks
constexpr int CHT   = Tt / NCH;          // 128 steps per chunk

// ---------------------------------------------------------------------------
// Scratch (device globals: allocation-free rule)
// ---------------------------------------------------------------------------
__device__ float g_h1[(size_t)MTOK * ENC];
__device__ float g_h2[(size_t)MTOK * ENC];
__device__ float g_z [(size_t)MTOK * LAT];
__device__ float g_z2[(size_t)MTOK * LAT];
__device__ float g_scan[(size_t)3 * Bsz * NCH * LAT];   // Ac | Bc | carry
// transposed (and tf32-rounded) weights: WT[n][k]
__device__ float g_t_ew1[(size_t)ENC * STATE];
__device__ float g_t_ew2[(size_t)ENC * ENC];
__device__ float g_t_ew3[(size_t)LAT * ENC];
__device__ float g_t_dw1[(size_t)ENC * LAT];
__device__ float g_t_dw2[(size_t)ENC * ENC];
__device__ float g_t_dw3[(size_t)STATE * ENC];

// ---------------------------------------------------------------------------
// Helpers
// ---------------------------------------------------------------------------
__device__ __forceinline__ float rna_tf32(float x) {
    float r;
    asm("cvt.rna.tf32.f32 %0, %1;" : "=f"(r) : "f"(x));
    return r;
}
// fast tanh: tanh(x) = sign(x) * (1 - e^{-2|x|}) / (1 + e^{-2|x|}),  err ~1e-6
__device__ __forceinline__ float fast_tanh(float x) {
    float ax = fabsf(x);
    float e;
    asm("ex2.approx.f32 %0, %1;" : "=f"(e) : "f"(-2.8853900817779268f * ax));
    float r;
    asm("rcp.approx.f32 %0, %1;" : "=f"(r) : "f"(1.0f + e));
    float t = (1.0f - e) * r;
    return copysignf(t, x);
}
#define SWZ128(off) ((off) ^ (((off) >> 3) & 0x70))

#if HAS_TC
__device__ __forceinline__ uint32_t smem_u32(const void* p) {
    uint32_t a;
    asm("{ .reg .u64 t; cvta.to.shared.u64 t, %1; cvt.u32.u64 %0, t; }" : "=r"(a) : "l"(p));
    return a;
}
__device__ __forceinline__ uint32_t elect_one() {
    uint32_t p;
    asm volatile("{ .reg .pred p; elect.sync _|p, 0xFFFFFFFF; selp.b32 %0, 1, 0, p; }" : "=r"(p));
    return p;
}

// 64-bit SMEM descriptor: SW128, Blackwell, LBO=1, SBO=64 (128B rows, 8-row atom)
static constexpr uint64_t DESC_BASE_SW128 =
    (uint64_t(2) << 61) | (uint64_t(1) << 46) | (uint64_t(64) << 32) | (uint64_t(1) << 16);
__device__ __forceinline__ uint64_t make_desc(uint32_t addr) {
    return DESC_BASE_SW128 | ((uint64_t)(addr >> 4) & 0x3FFF);
}

#define MBAR_INIT(a, c) \
    asm volatile("mbarrier.init.shared.b64 [%0], %1;" :: "r"(a), "r"(c) : "memory")
#define MBAR_WAIT(a, ph) do {                                                   \
    uint32_t _m = (a), _p = (ph), _d;                                           \
    asm volatile("{ .reg .pred p; mbarrier.try_wait.parity.acquire.cta.shared::cta.b64 p, [%1], %2; selp.b32 %0, 1, 0, p; }" \
                 : "=r"(_d) : "r"(_m), "r"(_p) : "memory");                     \
    if (!_d) {                                                                  \
        asm volatile("{ .reg .pred P;\nWL_%=:\n mbarrier.try_wait.parity.acquire.cta.shared::cta.b64 P, [%0], %1, 0x989680;\n @P bra.uni WD_%=;\n bra.uni WL_%=;\nWD_%=:\n}" \
                     :: "r"(_m), "r"(_p) : "memory");                           \
    } } while (0)

#define TC_ALLOC(sa, n) \
    asm volatile("tcgen05.alloc.cta_group::1.sync.aligned.shared::cta.b32 [%0], %1;" :: "r"(sa), "r"(n) : "memory")
#define TC_RELINQ() \
    asm volatile("tcgen05.relinquish_alloc_permit.cta_group::1.sync.aligned;")
#define TC_DEALLOC(t, n) \
    asm volatile("tcgen05.dealloc.cta_group::1.sync.aligned.b32 %0, %1;" :: "r"(t), "r"(n))
#define TC_COMMIT(mb) \
    asm volatile("tcgen05.commit.cta_group::1.mbarrier::arrive::one.shared::cluster.b64 [%0];" :: "r"(mb) : "memory")
#define TC_WAIT_LD() asm volatile("tcgen05.wait::ld.sync.aligned;" ::: "memory")
#define TC_FENCE_AFTER() asm volatile("tcgen05.fence::after_thread_sync;" ::: "memory")
#define FENCE_ASYNC() asm volatile("fence.proxy.async.shared::cta;" ::: "memory")

#define CP_ASYNC16(dst, src) \
    asm volatile("cp.async.cg.shared.global [%0], [%1], 16;" :: "r"(dst), "l"(src) : "memory")
#define CP_COMMIT() asm volatile("cp.async.commit_group;" ::: "memory")
#define CP_WAIT0()  asm volatile("cp.async.wait_group 0;" ::: "memory")

#define TC_LD_X32(r, ta) \
    asm volatile("tcgen05.ld.sync.aligned.32x32b.x32.b32 " \
        "{%0,%1,%2,%3,%4,%5,%6,%7,%8,%9,%10,%11,%12,%13,%14,%15," \
        "%16,%17,%18,%19,%20,%21,%22,%23,%24,%25,%26,%27,%28,%29,%30,%31}, [%32];" \
        : "=r"((r)[0]),"=r"((r)[1]),"=r"((r)[2]),"=r"((r)[3]),"=r"((r)[4]),"=r"((r)[5]),"=r"((r)[6]),"=r"((r)[7]), \
          "=r"((r)[8]),"=r"((r)[9]),"=r"((r)[10]),"=r"((r)[11]),"=r"((r)[12]),"=r"((r)[13]),"=r"((r)[14]),"=r"((r)[15]), \
          "=r"((r)[16]),"=r"((r)[17]),"=r"((r)[18]),"=r"((r)[19]),"=r"((r)[20]),"=r"((r)[21]),"=r"((r)[22]),"=r"((r)[23]), \
          "=r"((r)[24]),"=r"((r)[25]),"=r"((r)[26]),"=r"((r)[27]),"=r"((r)[28]),"=r"((r)[29]),"=r"((r)[30]),"=r"((r)[31]) \
        : "r"(ta))

__device__ __forceinline__ void mma_tf32_ss(uint32_t d, uint64_t ad, uint64_t bd,
                                            uint32_t idesc, uint32_t en) {
    asm volatile(
        "{\n\t.reg .pred p;\n\tsetp.ne.u32 p, %5, 0;\n\t"
        "tcgen05.mma.cta_group::1.kind::tf32 [%0], %1, %2, %3, {%4, %4, %4, %4}, p;\n\t}"
        :: "r"(d), "l"(ad), "l"(bd), "r"(idesc), "r"(0u), "r"(en) : "memory");
}
#endif  // HAS_TC

// ---------------------------------------------------------------------------
// Weight transpose + tf32 rounding: out[n*K + k] = rna(in[k*N + n])
// ---------------------------------------------------------------------------
__global__ void transpose_round(const float* __restrict__ in, float* __restrict__ out,
                                int K, int N) {
    __shared__ float t[32][33];
    const int kb = blockIdx.x * 32, nb = blockIdx.y * 32;
    const int x = threadIdx.x, y = threadIdx.y;  // 32x8
#pragma unroll
    for (int i = y; i < 32; i += 8)
        t[i][x] = rna_tf32(in[(size_t)(kb + i) * N + nb + x]);
    __syncthreads();
#pragma unroll
    for (int i = y; i < 32; i += 8)
        out[(size_t)(nb + i) * K + kb + x] = t[x][i];
}

// ---------------------------------------------------------------------------
// GEMM:  C[M,N] = act(A[M,K] @ W[K,N] + bias)
// A: row-major, stride lda.  BT: pre-transposed, tf32-rounded W^T [N][K].
// tcgen05 tf32 on sm_103a (cp.async fills; A pre-rounded unless ROUND_A);
// SIMT fallback body otherwise (same semantics).
// SKIP: encoder dead-work elimination — CTA's 128-token slab is needed only
// if its in-batch t-range touches t<=nwarmup (or contains t==0 for scan init).
// ---------------------------------------------------------------------------
template<int NT, bool TANH, bool HASBIAS, bool ROUND_OUT, bool ROUND_A, bool SKIP>
__global__ __launch_bounds__(256, 2)
void tc_gemm(const float* __restrict__ A, int lda,
             const float* __restrict__ BT,
             const float* __restrict__ bias,
             float* __restrict__ C, int N, int K,
             const int* __restrict__ nwp)
{
    const int tid = threadIdx.x;
    const int nb = blockIdx.x * NT;
    const int mb = blockIdx.y * 128;

    if (SKIP) {
        const int tlo = (blockIdx.y & (NCH - 1)) * 128;  // 16 CTAs per batch row
        if (tlo != 0 && tlo > __ldg(nwp)) return;
    }

#if HAS_TC
    extern __shared__ char dynsm[];
    const uint32_t smem_base = smem_u32(dynsm);
    const int wid = tid >> 5, lane = tid & 31;

    constexpr int ABYTES = 128 * 128;        // 16KB (128 rows x 32 tf32)
    constexpr int BBYTES = NT * 128;
    constexpr int BUFB   = ABYTES + BBYTES;

    const uint32_t s_tmemptr = smem_base;
    const uint32_t s_mbar0   = smem_base + 8;
    const uint32_t s_mbar1   = smem_base + 16;
    const uint32_t s_buf0    = (smem_base + 1024 + 1023) & ~1023u;  // 1KB aligned
    char* buf_ptr = dynsm + (s_buf0 - smem_base);

    if (tid == 0) { MBAR_INIT(s_mbar0, 1); MBAR_INIT(s_mbar1, 1); }
    if (wid == 0) { TC_ALLOC(s_tmemptr, NT); TC_RELINQ(); }
    __syncthreads();
    uint32_t tmem;
    asm volatile("ld.shared.b32 %0, [%1];" : "=r"(tmem) : "r"(s_tmemptr));

    const int KT = K >> 5;
    int ph0 = 0, ph1 = 0;
    constexpr uint32_t IDESC =
        (1u << 4) | (2u << 7) | (2u << 10) | ((NT / 8) << 17) | (8u << 24);

    for (int t = 0; t < KT; ++t) {
        const int buf = t & 1;
        const uint32_t sb = s_buf0 + buf * BUFB;
        char* sp = buf_ptr + buf * BUFB;

        if (t >= 2) {
            if (buf == 0) { MBAR_WAIT(s_mbar0, ph0); ph0 ^= 1; }
            else          { MBAR_WAIT(s_mbar1, ph1); ph1 ^= 1; }
        }

        // fill A tile: 128 rows x 32 cols
        const float* Ag = A + (size_t)mb * lda + t * 32;
        if (ROUND_A) {
#pragma unroll
            for (int i = 0; i < 4; i++) {
                const int idx = tid + i * 256;         // 0..1023 float4s
                const int row = idx >> 3, c4 = idx & 7;
                float4 v = *reinterpret_cast<const float4*>(Ag + (size_t)row * lda + c4 * 4);
                v.x = rna_tf32(v.x); v.y = rna_tf32(v.y);
                v.z = rna_tf32(v.z); v.w = rna_tf32(v.w);
                const uint32_t off = SWZ128((uint32_t)(row * 128 + c4 * 16));
                *reinterpret_cast<float4*>(sp + off) = v;
            }
        } else {
#pragma unroll
            for (int i = 0; i < 4; i++) {
                const int idx = tid + i * 256;
                const int row = idx >> 3, c16 = idx & 7;
                CP_ASYNC16(sb + SWZ128((uint32_t)(row * 128 + c16 * 16)),
                           Ag + (size_t)row * lda + c16 * 4);
            }
        }
        // fill B tile: NT rows x 32 cols from WT (already rounded)
        const float* Bg = BT + (size_t)nb * K + t * 32;
#pragma unroll
        for (int i = 0; i < NT / 32; i++) {
            const int idx = tid + i * 256;
            const int row = idx >> 3, c16 = idx & 7;
            CP_ASYNC16(sb + ABYTES + SWZ128((uint32_t)(row * 128 + c16 * 16)),
                       Bg + (size_t)row * K + c16 * 4);
        }
        CP_COMMIT();
        CP_WAIT0();
        __syncthreads();
        FENCE_ASYNC();

        if (wid == 0 && elect_one()) {
            const uint64_t ad = make_desc(sb);
            const uint64_t bd = make_desc(sb + ABYTES);
#pragma unroll
            for (int s = 0; s < 4; s++)            // 4 x K=8 tf32 MMAs
                mma_tf32_ss(tmem, ad + s * 2, bd + s * 2, IDESC,
                            (t > 0 || s > 0) ? 1u : 0u);
            if (buf == 0) TC_COMMIT(s_mbar0); else TC_COMMIT(s_mbar1);
        }
    }

    // drain outstanding MMA groups
    if (KT >= 2) {
        const int b = (KT - 2) & 1;
        if (b == 0) { MBAR_WAIT(s_mbar0, ph0); ph0 ^= 1; }
        else        { MBAR_WAIT(s_mbar1, ph1); ph1 ^= 1; }
    }
    {
        const int b = (KT - 1) & 1;
        if (b == 0) { MBAR_WAIT(s_mbar0, ph0); ph0 ^= 1; }
        else        { MBAR_WAIT(s_mbar1, ph1); ph1 ^= 1; }
    }
    TC_FENCE_AFTER();

    // epilogue: warps 0-3 cols [0,NT/2), warps 4-7 cols [NT/2,NT)
    const int half = wid >> 2;
    const int grow = mb + (wid & 3) * 32 + lane;
#pragma unroll
    for (int cc = 0; cc < NT / 2; cc += 32) {
        const int c0 = half * (NT / 2) + cc;
        uint32_t regs[32];
        TC_LD_X32(regs, tmem + c0);
        TC_WAIT_LD();
        float* Crow = C + (size_t)grow * N + nb + c0;
#pragma unroll
        for (int q = 0; q < 8; q++) {
            float4 o;
            float a0 = __uint_as_float(regs[4 * q + 0]);
            float a1 = __uint_as_float(regs[4 * q + 1]);
            float a2 = __uint_as_float(regs[4 * q + 2]);
            float a3 = __uint_as_float(regs[4 * q + 3]);
            if (HASBIAS) {
                a0 += bias[nb + c0 + 4 * q + 0];
                a1 += bias[nb + c0 + 4 * q + 1];
                a2 += bias[nb + c0 + 4 * q + 2];
                a3 += bias[nb + c0 + 4 * q + 3];
            }
            if (TANH) {
                a0 = fast_tanh(a0); a1 = fast_tanh(a1);
                a2 = fast_tanh(a2); a3 = fast_tanh(a3);
            }
            if (ROUND_OUT) {
                a0 = rna_tf32(a0); a1 = rna_tf32(a1);
                a2 = rna_tf32(a2); a3 = rna_tf32(a3);
            }
            o.x = a0; o.y = a1; o.z = a2; o.w = a3;
            *reinterpret_cast<float4*>(Crow + 4 * q) = o;
        }
    }
    __syncthreads();
    if (wid == 0) TC_DEALLOC(tmem, NT);

#else  // ---------------- SIMT fallback body (non-a pass) ----------------
    __shared__ float As[8][128];
    __shared__ float Bs[8][128];

    const int aRow = tid >> 1, aCol = (tid & 1) << 2;   // A loads
    const int bRow = tid >> 1, bCol = (tid & 1) << 2;   // BT loads (along K)
    const int tr = (tid >> 4) << 3, tc = (tid & 15) << 3;

    for (int sub = 0; sub < NT / 128; ++sub) {
        const int nb2 = nb + sub * 128;
        const float* Ab  = A + (size_t)mb * lda;
        const float* BTb = BT + (size_t)nb2 * K;

        float acc[8][8];
#pragma unroll
        for (int i = 0; i < 8; i++)
#pragma unroll
            for (int j = 0; j < 8; j++) acc[i][j] = 0.0f;

        for (int kt = 0; kt < K; kt += 8) {
            float4 av = *reinterpret_cast<const float4*>(Ab + (size_t)aRow * lda + kt + aCol);
            float4 bv = *reinterpret_cast<const float4*>(BTb + (size_t)bRow * K + kt + bCol);
            As[aCol + 0][aRow] = av.x; As[aCol + 1][aRow] = av.y;
            As[aCol + 2][aRow] = av.z; As[aCol + 3][aRow] = av.w;
            Bs[bCol + 0][bRow] = bv.x; Bs[bCol + 1][bRow] = bv.y;
            Bs[bCol + 2][bRow] = bv.z; Bs[bCol + 3][bRow] = bv.w;
            __syncthreads();
#pragma unroll
            for (int k = 0; k < 8; k++) {
                float4 a0 = *reinterpret_cast<const float4*>(&As[k][tr]);
                float4 a1 = *reinterpret_cast<const float4*>(&As[k][tr + 4]);
                float4 b0 = *reinterpret_cast<const float4*>(&Bs[k][tc]);
                float4 b1 = *reinterpret_cast<const float4*>(&Bs[k][tc + 4]);
                float am[8] = {a0.x, a0.y, a0.z, a0.w, a1.x, a1.y, a1.z, a1.w};
                float bn[8] = {b0.x, b0.y, b0.z, b0.w, b1.x, b1.y, b1.z, b1.w};
#pragma unroll
                for (int i = 0; i < 8; i++)
#pragma unroll
                    for (int j = 0; j < 8; j++)
                        acc[i][j] = fmaf(am[i], bn[j], acc[i][j]);
            }
            __syncthreads();
        }
        float* Cb = C + (size_t)(mb + tr) * N + nb2 + tc;
#pragma unroll
        for (int i = 0; i < 8; i++)
#pragma unroll
            for (int j = 0; j < 8; j++) {
                float v = acc[i][j];
                if (HASBIAS) v += bias[nb2 + tc + j];
                if (TANH)    v = fast_tanh(v);
                if (ROUND_OUT) v = rna_tf32(v);
                Cb[(size_t)i * N + j] = v;
            }
    }
#endif
}

// ---------------------------------------------------------------------------
// Chunked scan with fused Bu:
//   bu[b,t,l] = sum_k u[b,t,k] * Bw[k,l]  (K=16, computed on the fly)
//   t <= nw : state = a*z[t] + bu     (chain cut)
//   t >  nw : state = a*state + bu
// Pass1 (WRITE=0): per-chunk affine (A,B) with incoming-state x: state=A*x+B
// Pass2:           serial 16-step carry combine per (b,l); carry_0 = z[b,0,l]
// Pass3 (WRITE=1): replay chunk from carry_in; write tf32-rounded z2
// ---------------------------------------------------------------------------
template<bool WRITE>
__global__ void scan_chunk(const float* __restrict__ pin,
                           const float* __restrict__ z,
                           const float* __restrict__ Bw,
                           const float* __restrict__ a_diag,
                           const int*   __restrict__ nwp,
                           float* __restrict__ Ac, float* __restrict__ Bc,
                           const float* __restrict__ carry,
                           float* __restrict__ z2)
{
    __shared__ float u_s[CHT][16];       // 8KB chunk of u
    const int l = threadIdx.x;           // 0..255
    const int b = blockIdx.x;            // batch
    const int c = blockIdx.y;            // chunk
    const int nw = __ldg(nwp);

    float a = a_diag[l];
    a = fminf(0.95f, fmaxf(-0.95f, a));

    float bw[16];
#pragma unroll
    for (int k = 0; k < 16; k++) bw[k] = Bw[k * LAT + l];

    {   // load this chunk's u rows (CHT x 16 floats)
        const float* ub = pin + ((size_t)(b * Tt + c * CHT)) * INW + STATE + ACTd;
        for (int j = l; j < CHT * 4; j += 256) {
            const int i = j >> 2, k4 = j & 3;
            float4 v = *reinterpret_cast<const float4*>(ub + (size_t)i * INW + k4 * 4);
            *reinterpret_cast<float4*>(&u_s[i][k4 * 4]) = v;
        }
    }
    __syncthreads();

    const size_t zbase = ((size_t)(b * Tt + c * CHT)) * LAT + l;
    float Aacc = 1.0f, Bacc = 0.0f, st = 0.0f;
    if (WRITE) st = carry[((size_t)(b * NCH + c)) * LAT + l];

    for (int i = 0; i < CHT; ++i) {
        const int t = c * CHT + i;
        float4 u0 = *reinterpret_cast<const float4*>(&u_s[i][0]);
        float4 u1 = *reinterpret_cast<const float4*>(&u_s[i][4]);
        float4 u2 = *reinterpret_cast<const float4*>(&u_s[i][8]);
        float4 u3 = *reinterpret_cast<const float4*>(&u_s[i][12]);
        float bu = u0.x * bw[0];
        bu = fmaf(u0.y, bw[1],  bu); bu = fmaf(u0.z, bw[2],  bu);
        bu = fmaf(u0.w, bw[3],  bu); bu = fmaf(u1.x, bw[4],  bu);
        bu = fmaf(u1.y, bw[5],  bu); bu = fmaf(u1.z, bw[6],  bu);
        bu = fmaf(u1.w, bw[7],  bu); bu = fmaf(u2.x, bw[8],  bu);
        bu = fmaf(u2.y, bw[9],  bu); bu = fmaf(u2.z, bw[10], bu);
        bu = fmaf(u2.w, bw[11], bu); bu = fmaf(u3.x, bw[12], bu);
        bu = fmaf(u3.y, bw[13], bu); bu = fmaf(u3.z, bw[14], bu);
        bu = fmaf(u3.w, bw[15], bu);

        if (WRITE) {
            float inp = (t <= nw) ? z[zbase + (size_t)i * LAT] : st;
            st = fmaf(a, inp, bu);
            z2[zbase + (size_t)i * LAT] = rna_tf32(st);
        } else {
            if (t <= nw) {
                Aacc = 0.0f;
                Bacc = fmaf(a, z[zbase + (size_t)i * LAT], bu);
            } else {
                Aacc *= a;
                Bacc = fmaf(a, Bacc, bu);
            }
        }
    }
    if (!WRITE) {
        Ac[((size_t)(b * NCH + c)) * LAT + l] = Aacc;
        Bc[((size_t)(b * NCH + c)) * LAT + l] = Bacc;
    }
}

__global__ void scan_carry(const float* __restrict__ z,
                           const float* __restrict__ Ac,
                           const float* __restrict__ Bc,
                           float* __restrict__ carry)
{
    const int l = threadIdx.x;   // 0..255
    const int b = blockIdx.x;
    float cv = z[((size_t)b * Tt) * LAT + l];   // scan init = z[:,0,:]
#pragma unroll
    for (int c = 0; c < NCH; c++) {
        const size_t idx = ((size_t)(b * NCH + c)) * LAT + l;
        carry[idx] = cv;
        cv = fmaf(Ac[idx], cv, Bc[idx]);
    }
}

// ---------------------------------------------------------------------------
// Launch
// ---------------------------------------------------------------------------
extern "C" void kernel_launch(void* const* d_in, const int* in_sizes, int n_in,
                              void* d_out, int out_size)
{
    (void)in_sizes; (void)n_in; (void)out_size;
    const float* pin   = (const float*)d_in[0];
    const float* ew1   = (const float*)d_in[1];
    const float* eb1   = (const float*)d_in[2];
    const float* ew2   = (const float*)d_in[3];
    const float* eb2   = (const float*)d_in[4];
    const float* ew3   = (const float*)d_in[5];
    const float* eb3   = (const float*)d_in[6];
    const float* adiag = (const float*)d_in[7];
    const float* Bw    = (const float*)d_in[8];
    const float* dw1   = (const float*)d_in[9];
    const float* db1   = (const float*)d_in[10];
    const float* dw2   = (const float*)d_in[11];
    const float* db2   = (const float*)d_in[12];
    const float* dw3   = (const float*)d_in[13];
    const float* db3   = (const float*)d_in[14];
    const int*   nw    = (const int*)d_in[15];
    float* out = (float*)d_out;

    float *h1, *h2, *z, *z2, *scan;
    float *t_ew1, *t_ew2, *t_ew3, *t_dw1, *t_dw2, *t_dw3;
    cudaGetSymbolAddress((void**)&h1, g_h1);
    cudaGetSymbolAddress((void**)&h2, g_h2);
    cudaGetSymbolAddress((void**)&z,  g_z);
    cudaGetSymbolAddress((void**)&z2, g_z2);
    cudaGetSymbolAddress((void**)&scan, g_scan);
    cudaGetSymbolAddress((void**)&t_ew1, g_t_ew1);
    cudaGetSymbolAddress((void**)&t_ew2, g_t_ew2);
    cudaGetSymbolAddress((void**)&t_ew3, g_t_ew3);
    cudaGetSymbolAddress((void**)&t_dw1, g_t_dw1);
    cudaGetSymbolAddress((void**)&t_dw2, g_t_dw2);
    cudaGetSymbolAddress((void**)&t_dw3, g_t_dw3);

    float* Ac    = scan;
    float* Bc    = scan + (size_t)Bsz * NCH * LAT;
    float* carry = scan + (size_t)2 * Bsz * NCH * LAT;

    // dynamic smem: 2KB header/align slack + 2 double buffers
    const int SMEM256 = 2048 + 2 * (128 * 128 + 256 * 128);  // 100352
    const int SMEM128 = 2048 + 2 * (128 * 128 + 128 * 128);  // 67584
    cudaFuncSetAttribute(tc_gemm<256, true,  true, true,  true,  true>,
                         cudaFuncAttributeMaxDynamicSharedMemorySize, SMEM256);
    cudaFuncSetAttribute(tc_gemm<256, true,  true, true,  false, true>,
                         cudaFuncAttributeMaxDynamicSharedMemorySize, SMEM256);
    cudaFuncSetAttribute(tc_gemm<256, true,  true, false, false, true>,
                         cudaFuncAttributeMaxDynamicSharedMemorySize, SMEM256);
    cudaFuncSetAttribute(tc_gemm<256, true,  true, true,  false, false>,
                         cudaFuncAttributeMaxDynamicSharedMemorySize, SMEM256);
    cudaFuncSetAttribute(tc_gemm<128, false, true, false, false, false>,
                         cudaFuncAttributeMaxDynamicSharedMemorySize, SMEM128);

    const dim3 tb(32, 8);
    // transpose + tf32-round weights: in[K,N] -> out[N,K]
    transpose_round<<<dim3(STATE / 32, ENC / 32), tb>>>(ew1, t_ew1, STATE, ENC);
    transpose_round<<<dim3(ENC / 32,   ENC / 32), tb>>>(ew2, t_ew2, ENC,   ENC);
    transpose_round<<<dim3(ENC / 32,   LAT / 32), tb>>>(ew3, t_ew3, ENC,   LAT);
    transpose_round<<<dim3(LAT / 32,   ENC / 32), tb>>>(dw1, t_dw1, LAT,   ENC);
    transpose_round<<<dim3(ENC / 32,   ENC / 32), tb>>>(dw2, t_dw2, ENC,   ENC);
    transpose_round<<<dim3(ENC / 32, STATE / 32), tb>>>(dw3, t_dw3, ENC,   STATE);

    const int MBLK = MTOK / 128;  // 512

    // Encoder (CTA-skipped past warmup; outputs tf32-rounded except z)
    tc_gemm<256, true, true, true,  true,  true><<<dim3(ENC / 256, MBLK), 256, SMEM256>>>(
        pin, INW, t_ew1, eb1, h1, ENC, STATE, nw);
    tc_gemm<256, true, true, true,  false, true><<<dim3(ENC / 256, MBLK), 256, SMEM256>>>(
        h1, ENC, t_ew2, eb2, h2, ENC, ENC, nw);
    tc_gemm<256, true, true, false, false, true><<<dim3(LAT / 256, MBLK), 256, SMEM256>>>(
        h2, ENC, t_ew3, eb3, z, LAT, ENC, nw);

    // Chunked scan with fused Bu
    scan_chunk<false><<<dim3(Bsz, NCH), 256>>>(pin, z, Bw, adiag, nw,
                                               Ac, Bc, nullptr, nullptr);
    scan_carry<<<Bsz, LAT>>>(z, Ac, Bc, carry);
    scan_chunk<true ><<<dim3(Bsz, NCH), 256>>>(pin, z, Bw, adiag, nw,
                                               nullptr, nullptr, carry, z2);

    // Decoder
    tc_gemm<256, true,  true, true,  false, false><<<dim3(ENC / 256, MBLK), 256, SMEM256>>>(
        z2, LAT, t_dw1, db1, h1, ENC, LAT, nw);
    tc_gemm<256, true,  true, true,  false, false><<<dim3(ENC / 256, MBLK), 256, SMEM256>>>(
        h1, ENC, t_dw2, db2, h2, ENC, ENC, nw);
    tc_gemm<128, false, true, false, false, false><<<dim3(STATE / 128, MBLK), 256, SMEM128>>>(
        h2, ENC, t_dw3, db3, out, STATE, ENC, nw);
}